// round 5
// baseline (speedup 1.0000x reference)
#include <cuda_runtime.h>
#include <cuda_bf16.h>
#include <cuda_fp16.h>
#include <mma.h>
#include <cstdint>
#include <cstddef>

using namespace nvcuda;

// Problem dims
#define B_DIM 16
#define T_DIM 512
#define D_DIM 256
#define H_DIM 256
#define SCALE_C 0.1f
#define NBLK_SCAN 128

// ---------------- static device scratch (no allocation allowed) ----------------
__device__ __half g_P[(size_t)B_DIM * T_DIM * H_DIM * H_DIM];  // 1 GB, P[bt][o*256+h], fp16
__device__ float g_BT[(size_t)H_DIM * H_DIM * D_DIM];          // 64 MB, B_w transposed: [(o*256+h)][d], fp32
__device__ float g_h[2][B_DIM * H_DIM];                        // double-buffered hidden state
__device__ unsigned g_count;                                   // grid barrier
__device__ unsigned g_gen;

// ---------------- transpose B_w [o][d][h] -> g_BT [(o*256+h)][d] (fp32) ----------------
__global__ void transpose_B_kernel(const float* __restrict__ Bw) {
    __shared__ float tile[32][33];
    int o = blockIdx.z;
    int h0 = blockIdx.x * 32, d0 = blockIdx.y * 32;
    int tx = threadIdx.x, ty = threadIdx.y;
    #pragma unroll
    for (int i = 0; i < 32; i += 8)
        tile[ty + i][tx] = Bw[(size_t)o * 65536 + (size_t)(d0 + ty + i) * 256 + h0 + tx];
    __syncthreads();
    #pragma unroll
    for (int i = 0; i < 32; i += 8)
        g_BT[((size_t)o * 256 + h0 + ty + i) * 256 + d0 + tx] = tile[tx][ty + i];
}

// ---------------- big GEMM: P[8192,65536] = x[8192,256] * g_BT^T  (tf32 wmma, fp32 acc, fp16 out) ----------------
// Grid: x = M-tile (64), y = N-tile (512)  -> all M-tiles of one N-tile co-scheduled;
// x (8 MB) stays L2-resident, each B tile read from DRAM ~once.
__global__ __launch_bounds__(256) void gemm_P_kernel(const float* __restrict__ x) {
    __shared__ __align__(16) float As[128][36];
    __shared__ __align__(16) float Bs[128][36];
    __shared__ __align__(16) float scr[8][256];

    int tid = threadIdx.x;
    int wid = tid >> 5, lane = tid & 31;
    int gm0 = blockIdx.x * 128;
    int gn0 = blockIdx.y * 128;

    wmma::fragment<wmma::accumulator, 16, 16, 8, float> acc[4][2];
    #pragma unroll
    for (int mi = 0; mi < 4; mi++)
        #pragma unroll
        for (int ni = 0; ni < 2; ni++)
            wmma::fill_fragment(acc[mi][ni], 0.0f);

    int wm = (wid >> 2) * 64;  // warp M offset within tile
    int wn = (wid & 3) * 32;   // warp N offset within tile

    for (int kt = 0; kt < 8; kt++) {
        int k0 = kt * 32;
        // load 128x32 fp32 tiles of A and B^T: 1024 float4's, 256 threads
        #pragma unroll
        for (int i = tid; i < 1024; i += 256) {
            int r = i >> 3, c = (i & 7) * 4;
            *(float4*)&As[r][c] = *(const float4*)&x[(size_t)(gm0 + r) * 256 + k0 + c];
            *(float4*)&Bs[r][c] = *(const float4*)&g_BT[(size_t)(gn0 + r) * 256 + k0 + c];
        }
        __syncthreads();
        #pragma unroll
        for (int kk = 0; kk < 32; kk += 8) {
            wmma::fragment<wmma::matrix_a, 16, 16, 8, wmma::precision::tf32, wmma::row_major> af[4];
            wmma::fragment<wmma::matrix_b, 16, 16, 8, wmma::precision::tf32, wmma::col_major> bf[2];
            #pragma unroll
            for (int mi = 0; mi < 4; mi++) {
                wmma::load_matrix_sync(af[mi], &As[wm + mi * 16][kk], 36);
                #pragma unroll
                for (int e = 0; e < af[mi].num_elements; e++)
                    af[mi].x[e] = wmma::__float_to_tf32(af[mi].x[e]);
            }
            #pragma unroll
            for (int ni = 0; ni < 2; ni++) {
                wmma::load_matrix_sync(bf[ni], &Bs[wn + ni * 16][kk], 36);
                #pragma unroll
                for (int e = 0; e < bf[ni].num_elements; e++)
                    bf[ni].x[e] = wmma::__float_to_tf32(bf[ni].x[e]);
            }
            #pragma unroll
            for (int mi = 0; mi < 4; mi++)
                #pragma unroll
                for (int ni = 0; ni < 2; ni++)
                    wmma::mma_sync(acc[mi][ni], af[mi], bf[ni], acc[mi][ni]);
        }
        __syncthreads();
    }

    // epilogue: fp32 acc -> fp16 -> g_P
    #pragma unroll
    for (int mi = 0; mi < 4; mi++) {
        #pragma unroll
        for (int ni = 0; ni < 2; ni++) {
            wmma::store_matrix_sync(&scr[wid][0], acc[mi][ni], 16, wmma::mem_row_major);
            __syncwarp();
            int r = lane >> 1, c0 = (lane & 1) * 8;
            const float* s = &scr[wid][r * 16 + c0];
            union { __half b[8]; uint4 v; } u;
            #pragma unroll
            for (int j = 0; j < 8; j++) u.b[j] = __float2half_rn(s[j]);
            size_t off = (size_t)(gm0 + wm + mi * 16 + r) * 65536 + (size_t)(gn0 + wn + ni * 16 + c0);
            *(uint4*)&g_P[off] = u.v;
            __syncwarp();
        }
    }
}

// ---------------- grid barrier (all 128 blocks co-resident) ----------------
__device__ __forceinline__ void grid_barrier(unsigned target) {
    __syncthreads();
    if (threadIdx.x == 0) {
        __threadfence();
        unsigned old = atomicAdd(&g_count, 1u);
        if (old == (unsigned)(NBLK_SCAN - 1)) {
            atomicExch(&g_count, 0u);
            __threadfence();
            atomicExch(&g_gen, target);
        } else {
            volatile unsigned* vg = &g_gen;
            while ((int)(*vg - target) < 0) { }
            __threadfence();
        }
    }
    __syncthreads();
}

__device__ __forceinline__ float sigmoidf_(float v) { return 1.0f / (1.0f + expf(-v)); }

// ---------------- persistent scan kernel ----------------
// 128 blocks x 256 threads. Block = (o-group of 4) x (b-group of 8). Warp = one b, 4 o's.
__global__ __launch_bounds__(256) void scan_kernel(
    const float* __restrict__ x,
    const float* __restrict__ Ww, const float* __restrict__ Wb,
    const float* __restrict__ Uw, const float* __restrict__ Ub,
    const float* __restrict__ Bbias,
    float* __restrict__ out, int out_size)
{
    __shared__ float Us[16][256];   // rows: p*4+gi -> U_w[gi*256 + o0+p][:]
    __shared__ float Ws[16][256];
    __shared__ float cb_s[16];      // W_b + U_b combined
    __shared__ float bb_s[4];       // B_b
    __shared__ unsigned s_base;

    int tid = threadIdx.x;
    int wid = tid >> 5, lane = tid & 31;
    int bid = blockIdx.x;
    int o0 = (bid & 63) * 4;
    int b  = (bid >> 6) * 8 + wid;

    if (tid == 0) s_base = g_gen;   // persists across graph replays; relative targets

    for (int i = tid; i < 4096; i += 256) {
        int r = i >> 8, k = i & 255;
        int p = r >> 2, gi = r & 3;
        int grow = gi * 256 + o0 + p;
        Us[r][k] = Uw[(size_t)grow * 256 + k];
        Ws[r][k] = Ww[(size_t)grow * 256 + k];
    }
    if (tid < 16) {
        int p = tid >> 2, gi = tid & 3;
        int grow = gi * 256 + o0 + p;
        cb_s[tid] = Wb[grow] + Ub[grow];
    }
    if (tid < 4) bb_s[tid] = Bbias[o0 + tid];
    __syncthreads();
    unsigned base = s_base;

    float c[4] = {0.f, 0.f, 0.f, 0.f};
    if (lane < 4) g_h[0][b * 256 + o0 + lane] = 0.f;
    unsigned gen = base + 1;
    grid_barrier(gen);

    for (int t = 0; t < T_DIM; t++) {
        // --- pre-barrier: x-only work + P prefetch (overlaps other blocks' tail) ---
        float xr[8];
        const float* xp = x + ((size_t)b * T_DIM + t) * 256 + lane * 8;
        *(float4*)&xr[0] = *(const float4*)xp;
        *(float4*)&xr[4] = *(const float4*)(xp + 4);

        uint4 pr[4];
        const __half* pp = g_P + (size_t)(b * T_DIM + t) * 65536 + (size_t)o0 * 256 + lane * 8;
        #pragma unroll
        for (int p = 0; p < 4; p++) pr[p] = *(const uint4*)(pp + (size_t)p * 256);

        float gs[16];
        #pragma unroll
        for (int r = 0; r < 16; r++) {
            float4 w0 = *(const float4*)&Ws[r][lane * 8];
            float4 w1 = *(const float4*)&Ws[r][lane * 8 + 4];
            gs[r] = w0.x * xr[0] + w0.y * xr[1] + w0.z * xr[2] + w0.w * xr[3]
                  + w1.x * xr[4] + w1.y * xr[5] + w1.z * xr[6] + w1.w * xr[7];
        }

        gen++;
        grid_barrier(gen);          // h(t-1) now visible

        int rb = t & 1;
        float hr[8];
        const float* hp = &g_h[rb][b * 256 + lane * 8];
        *(float4*)&hr[0] = *(const float4*)hp;
        *(float4*)&hr[4] = *(const float4*)(hp + 4);

        #pragma unroll
        for (int r = 0; r < 16; r++) {
            float4 u0 = *(const float4*)&Us[r][lane * 8];
            float4 u1 = *(const float4*)&Us[r][lane * 8 + 4];
            gs[r] += u0.x * hr[0] + u0.y * hr[1] + u0.z * hr[2] + u0.w * hr[3]
                   + u1.x * hr[4] + u1.y * hr[5] + u1.z * hr[6] + u1.w * hr[7];
        }

        float ms[4];
        #pragma unroll
        for (int p = 0; p < 4; p++) {
            const __half2* pb = (const __half2*)&pr[p];
            float s = 0.f;
            #pragma unroll
            for (int j = 0; j < 4; j++) {
                float2 f = __half22float2(pb[j]);
                s += f.x * hr[2 * j] + f.y * hr[2 * j + 1];
            }
            ms[p] = s;
        }

        // warp reductions (all lanes end with full sums)
        #pragma unroll
        for (int off = 16; off > 0; off >>= 1) {
            #pragma unroll
            for (int r = 0; r < 16; r++) gs[r] += __shfl_xor_sync(0xffffffffu, gs[r], off);
            #pragma unroll
            for (int p = 0; p < 4; p++) ms[p] += __shfl_xor_sync(0xffffffffu, ms[p], off);
        }

        float hn[4];
        #pragma unroll
        for (int p = 0; p < 4; p++) {
            float iv = sigmoidf_(gs[p * 4 + 0] + cb_s[p * 4 + 0]);
            float fv = sigmoidf_(gs[p * 4 + 1] + cb_s[p * 4 + 1]);
            float ov = sigmoidf_(gs[p * 4 + 2] + cb_s[p * 4 + 2]);
            float gv = tanhf(gs[p * 4 + 3] + cb_s[p * 4 + 3]);
            float mv = tanhf(ms[p] + bb_s[p]);
            c[p] = fv * c[p] + iv * gv + SCALE_C * mv;
            hn[p] = ov * tanhf(c[p]);
        }

        if (lane < 4) {
            float v = hn[lane];
            g_h[rb ^ 1][b * 256 + o0 + lane] = v;
            out[((size_t)b * T_DIM + t) * 256 + o0 + lane] = v;
            if (t == T_DIM - 1) {
                size_t tail = (size_t)B_DIM * T_DIM * H_DIM;
                if (out_size >= (int)(tail + 2 * B_DIM * H_DIM)) {
                    out[tail + b * 256 + o0 + lane] = v;                       // final h
                    out[tail + B_DIM * H_DIM + b * 256 + o0 + lane] = c[lane]; // final c
                }
            }
        }
    }
}

// ---------------- launch ----------------
extern "C" void kernel_launch(void* const* d_in, const int* in_sizes, int n_in,
                              void* d_out, int out_size) {
    const float* x  = (const float*)d_in[0];
    const float* Ww = (const float*)d_in[1];
    const float* Wb = (const float*)d_in[2];
    const float* Uw = (const float*)d_in[3];
    const float* Ub = (const float*)d_in[4];
    const float* Bw = (const float*)d_in[5];
    const float* Bb = (const float*)d_in[6];
    float* out = (float*)d_out;

    transpose_B_kernel<<<dim3(8, 8, 256), dim3(32, 8)>>>(Bw);
    gemm_P_kernel<<<dim3(64, 512), 256>>>(x);
    scan_kernel<<<NBLK_SCAN, 256>>>(x, Ww, Wb, Uw, Ub, Bb, out, out_size);
}

// round 7
// speedup vs baseline: 1.7129x; 1.7129x over previous
#include <cuda_runtime.h>
#include <cuda_fp16.h>
#include <cstdint>
#include <cstddef>

// Problem dims
#define B_DIM 16
#define T_DIM 512
#define D_DIM 256
#define H_DIM 256
#define SCALE_C 0.1f

// GEMM tiling: 128x128 tile, K chunks of 64 (one 128B swizzle row per chunk)
#define TILE_M 128
#define TILE_N 128
#define KC 64
#define NCHUNK 4

// ---------------- static device scratch (no allocation allowed) ----------------
__device__ __half g_P[(size_t)B_DIM * T_DIM * H_DIM * H_DIM];   // 1 GB, P[bt][o*256+h], fp16
__device__ __half g_Xh[(size_t)B_DIM * T_DIM * D_DIM];          // 4 MB, x fp16
__device__ __half g_BTh[(size_t)H_DIM * H_DIM * D_DIM];         // 32 MB, B_w^T fp16: [(o*256+h)][d]
__device__ float g_h[2][B_DIM * H_DIM];                         // double-buffered hidden state
__device__ unsigned g_cnt[2 * 32];                              // split grid barrier (padded)
__device__ unsigned g_genA[2 * 32];

// ---------------- helpers ----------------
__device__ __forceinline__ uint32_t smem_u32(const void* p) {
    uint32_t a;
    asm("{ .reg .u64 t; cvta.to.shared.u64 t, %1; cvt.u32.u64 %0, t; }" : "=r"(a) : "l"(p));
    return a;
}
// swizzled offset within a 128B-row tile: row*128 + (kbyte ^ ((row<<4)&0x70))
__device__ __forceinline__ uint32_t swz(int row, int kbyte) {
    return (uint32_t)(row * 128 + (kbyte ^ ((row << 4) & 0x70)));
}
__device__ __forceinline__ void cp_async16(uint32_t saddr, const void* gaddr) {
    asm volatile("cp.async.cg.shared.global [%0], [%1], 16;" :: "r"(saddr), "l"(gaddr) : "memory");
}
#define CP_COMMIT() asm volatile("cp.async.commit_group;" ::: "memory")
#define CP_WAIT(n)  asm volatile("cp.async.wait_group %0;" :: "n"(n) : "memory")

__device__ __forceinline__ void ldsm_x4(uint32_t* r, uint32_t addr) {
    asm volatile("ldmatrix.sync.aligned.m8n8.x4.shared.b16 {%0,%1,%2,%3}, [%4];"
                 : "=r"(r[0]), "=r"(r[1]), "=r"(r[2]), "=r"(r[3]) : "r"(addr));
}
__device__ __forceinline__ void ldsm_x2(uint32_t* r, uint32_t addr) {
    asm volatile("ldmatrix.sync.aligned.m8n8.x2.shared.b16 {%0,%1}, [%2];"
                 : "=r"(r[0]), "=r"(r[1]) : "r"(addr));
}
__device__ __forceinline__ void mma16816(float* c, const uint32_t* a, const uint32_t* b) {
    asm volatile("mma.sync.aligned.m16n8k16.row.col.f32.f16.f16.f32 "
                 "{%0,%1,%2,%3}, {%4,%5,%6,%7}, {%8,%9}, {%0,%1,%2,%3};"
                 : "+f"(c[0]), "+f"(c[1]), "+f"(c[2]), "+f"(c[3])
                 : "r"(a[0]), "r"(a[1]), "r"(a[2]), "r"(a[3]), "r"(b[0]), "r"(b[1]));
}

// ---------------- prep kernels ----------------
__global__ void cvt_x_kernel(const float* __restrict__ x) {
    int n = B_DIM * T_DIM * D_DIM;
    for (int i = blockIdx.x * blockDim.x + threadIdx.x; i < n; i += gridDim.x * blockDim.x)
        g_Xh[i] = __float2half_rn(x[i]);
}

__global__ void transpose_B_kernel(const float* __restrict__ Bw) {
    __shared__ float tile[32][33];
    int o = blockIdx.z;
    int h0 = blockIdx.x * 32, d0 = blockIdx.y * 32;
    int tx = threadIdx.x, ty = threadIdx.y;
    #pragma unroll
    for (int i = 0; i < 32; i += 8)
        tile[ty + i][tx] = Bw[(size_t)o * 65536 + (size_t)(d0 + ty + i) * 256 + h0 + tx];
    __syncthreads();
    #pragma unroll
    for (int i = 0; i < 32; i += 8)
        g_BTh[((size_t)o * 256 + h0 + ty + i) * 256 + d0 + tx] = __float2half_rn(tile[tx][ty + i]);
}

// ---------------- fp16 mma.sync GEMM: P[8192,65536] = Xh * BTh^T ----------------
// 256 threads, 8 warps (2x4): warp tile 64x32. cp.async double-buffered K chunks.
// blockIdx.x = M-tile (64, fast) -> same-N blocks co-scheduled; x stays in L2.
#define CH_BYTES (128 * 128)                 // 16 KB per chunk per operand
#define SMEM_DYN (4 * CH_BYTES + 1024)

__global__ __launch_bounds__(256, 2) void gemm_P_kernel() {
    extern __shared__ char dynsmem[];
    uint32_t base = (smem_u32(dynsmem) + 1023u) & ~1023u;
    uint32_t aoff[2] = { base, base + CH_BYTES };
    uint32_t boff[2] = { base + 2 * CH_BYTES, base + 3 * CH_BYTES };

    int tid = threadIdx.x;
    int wid = tid >> 5, lane = tid & 31;
    int gm0 = blockIdx.x * TILE_M;
    int gn0 = blockIdx.y * TILE_N;
    int wm = (wid >> 2) * 64;
    int wn = (wid & 3) * 32;

    const __half* Asrc = g_Xh + (size_t)gm0 * 256;
    const __half* Bsrc = g_BTh + (size_t)gn0 * 256;

    // chunk loader: 128 rows x 64 halves (= 8 x 16B per row), 256 threads, 4 iters per operand
    auto load_chunk = [&](int kc, int buf) {
        int k0 = kc * KC;
        #pragma unroll
        for (int it = 0; it < 4; it++) {
            int i = tid + it * 256;
            int r = i >> 3, c16 = i & 7;
            cp_async16(aoff[buf] + swz(r, c16 * 16), &Asrc[(size_t)r * 256 + k0 + c16 * 8]);
        }
        #pragma unroll
        for (int it = 0; it < 4; it++) {
            int i = tid + it * 256;
            int r = i >> 3, c16 = i & 7;
            cp_async16(boff[buf] + swz(r, c16 * 16), &Bsrc[(size_t)r * 256 + k0 + c16 * 8]);
        }
        CP_COMMIT();
    };

    float acc[4][4][4];
    #pragma unroll
    for (int mi = 0; mi < 4; mi++)
        #pragma unroll
        for (int ni = 0; ni < 4; ni++)
            #pragma unroll
            for (int e = 0; e < 4; e++) acc[mi][ni][e] = 0.f;

    // per-lane ldmatrix row/k offsets
    int la = (lane & 7) + ((lane >> 3) & 1) * 8;   // A row-in-16
    int ka = ((lane >> 4) & 1) * 8;                // A k offset (halves)
    int lb = lane & 7;                             // B row-in-8 (lanes 0-15 used)
    int kb = ((lane >> 3) & 1) * 8;                // B k offset (halves)

    load_chunk(0, 0);

    #pragma unroll
    for (int kc = 0; kc < NCHUNK; kc++) {
        int buf = kc & 1;
        if (kc + 1 < NCHUNK) load_chunk(kc + 1, (kc + 1) & 1);
        if (kc + 1 < NCHUNK) { CP_WAIT(1); } else { CP_WAIT(0); }
        __syncthreads();

        uint32_t ab = aoff[buf], bb = boff[buf];
        #pragma unroll
        for (int ks = 0; ks < 4; ks++) {
            uint32_t afr[4][4], bfr[4][2];
            #pragma unroll
            for (int mi = 0; mi < 4; mi++) {
                int row = wm + mi * 16 + la;
                ldsm_x4(afr[mi], ab + swz(row, (ks * 16 + ka) * 2));
            }
            #pragma unroll
            for (int ni = 0; ni < 4; ni++) {
                int row = wn + ni * 8 + lb;
                ldsm_x2(bfr[ni], bb + swz(row, (ks * 16 + kb) * 2));
            }
            #pragma unroll
            for (int mi = 0; mi < 4; mi++)
                #pragma unroll
                for (int ni = 0; ni < 4; ni++)
                    mma16816(acc[mi][ni], afr[mi], bfr[ni]);
        }
        __syncthreads();
    }

    // epilogue: stage fp16 tile in smem (pitch 136 halves), then coalesced uint4 stores
    __half* stage = (__half*)(size_t)0;  // placeholder; use dynsmem via half ptr
    {
        __half* sm = (__half*)dynsmem;
        int q = lane >> 2, p = lane & 3;
        #pragma unroll
        for (int mi = 0; mi < 4; mi++)
            #pragma unroll
            for (int ni = 0; ni < 4; ni++) {
                int col = wn + ni * 8 + p * 2;
                int r0 = wm + mi * 16 + q;
                *(__half2*)&sm[r0 * 136 + col] =
                    __floats2half2_rn(acc[mi][ni][0], acc[mi][ni][1]);
                *(__half2*)&sm[(r0 + 8) * 136 + col] =
                    __floats2half2_rn(acc[mi][ni][2], acc[mi][ni][3]);
            }
        __syncthreads();
        #pragma unroll
        for (int j = 0; j < 8; j++) {
            int i = tid + j * 256;
            int r = i >> 4, c16 = i & 15;
            uint4 v = *(const uint4*)&sm[r * 136 + c16 * 8];
            *(uint4*)&g_P[(size_t)(gm0 + r) * 65536 + gn0 + c16 * 8] = v;
        }
    }
    (void)stage;
}

// ---------------- split grid barrier: two independent 64-block groups ----------------
__device__ __forceinline__ void grid_barrier(int grp, unsigned target) {
    __syncthreads();
    if (threadIdx.x == 0) {
        __threadfence();
        unsigned old = atomicAdd(&g_cnt[grp * 32], 1u);
        if (old == 63u) {
            atomicExch(&g_cnt[grp * 32], 0u);
            __threadfence();
            atomicExch(&g_genA[grp * 32], target);
        } else {
            volatile unsigned* vg = &g_genA[grp * 32];
            while ((int)(*vg - target) < 0) { }
            __threadfence();
        }
    }
    __syncthreads();
}

__device__ __forceinline__ float sigmoidf_(float v) { return 1.0f / (1.0f + expf(-v)); }

// ---------------- persistent scan kernel ----------------
// 128 blocks x 256 threads. Block = (o-group of 4) x (b-octet). Warp = one b, 4 o's.
// Blocks 0-63 handle b0-7, 64-127 handle b8-15 -> independent barrier groups.
__global__ __launch_bounds__(256) void scan_kernel(
    const float* __restrict__ x,
    const float* __restrict__ Ww, const float* __restrict__ Wb,
    const float* __restrict__ Uw, const float* __restrict__ Ub,
    const float* __restrict__ Bbias,
    float* __restrict__ out, int out_size)
{
    __shared__ float Us[16][256];
    __shared__ float Ws[16][256];
    __shared__ float cb_s[16];
    __shared__ float bb_s[4];
    __shared__ unsigned s_base;

    int tid = threadIdx.x;
    int wid = tid >> 5, lane = tid & 31;
    int bid = blockIdx.x;
    int grp = bid >> 6;
    int o0 = (bid & 63) * 4;
    int b  = grp * 8 + wid;

    if (tid == 0) s_base = g_genA[grp * 32];

    for (int i = tid; i < 4096; i += 256) {
        int r = i >> 8, k = i & 255;
        int p = r >> 2, gi = r & 3;
        int grow = gi * 256 + o0 + p;
        Us[r][k] = Uw[(size_t)grow * 256 + k];
        Ws[r][k] = Ww[(size_t)grow * 256 + k];
    }
    if (tid < 16) {
        int p = tid >> 2, gi = tid & 3;
        int grow = gi * 256 + o0 + p;
        cb_s[tid] = Wb[grow] + Ub[grow];
    }
    if (tid < 4) bb_s[tid] = Bbias[o0 + tid];
    __syncthreads();
    unsigned base = s_base;

    float c[4] = {0.f, 0.f, 0.f, 0.f};
    if (lane < 4) g_h[0][b * 256 + o0 + lane] = 0.f;
    unsigned gen = base + 1;
    grid_barrier(grp, gen);

    for (int t = 0; t < T_DIM; t++) {
        // pre-barrier: x-only gates + P prefetch
        float xr[8];
        const float* xp = x + ((size_t)b * T_DIM + t) * 256 + lane * 8;
        *(float4*)&xr[0] = *(const float4*)xp;
        *(float4*)&xr[4] = *(const float4*)(xp + 4);

        uint4 pr[4];
        const __half* pp = g_P + (size_t)(b * T_DIM + t) * 65536 + (size_t)o0 * 256 + lane * 8;
        #pragma unroll
        for (int p = 0; p < 4; p++) pr[p] = *(const uint4*)(pp + (size_t)p * 256);

        float gs[16];
        #pragma unroll
        for (int r = 0; r < 16; r++) {
            float4 w0 = *(const float4*)&Ws[r][lane * 8];
            float4 w1 = *(const float4*)&Ws[r][lane * 8 + 4];
            gs[r] = w0.x * xr[0] + w0.y * xr[1] + w0.z * xr[2] + w0.w * xr[3]
                  + w1.x * xr[4] + w1.y * xr[5] + w1.z * xr[6] + w1.w * xr[7];
        }

        gen++;
        grid_barrier(grp, gen);       // h(t-1) now visible

        int rb = t & 1;
        float hr[8];
        const float* hp = &g_h[rb][b * 256 + lane * 8];
        *(float4*)&hr[0] = *(const float4*)hp;
        *(float4*)&hr[4] = *(const float4*)(hp + 4);

        #pragma unroll
        for (int r = 0; r < 16; r++) {
            float4 u0 = *(const float4*)&Us[r][lane * 8];
            float4 u1 = *(const float4*)&Us[r][lane * 8 + 4];
            gs[r] += u0.x * hr[0] + u0.y * hr[1] + u0.z * hr[2] + u0.w * hr[3]
                   + u1.x * hr[4] + u1.y * hr[5] + u1.z * hr[6] + u1.w * hr[7];
        }

        float ms[4];
        #pragma unroll
        for (int p = 0; p < 4; p++) {
            const __half2* pb = (const __half2*)&pr[p];
            float s = 0.f;
            #pragma unroll
            for (int j = 0; j < 4; j++) {
                float2 f = __half22float2(pb[j]);
                s += f.x * hr[2 * j] + f.y * hr[2 * j + 1];
            }
            ms[p] = s;
        }

        #pragma unroll
        for (int off = 16; off > 0; off >>= 1) {
            #pragma unroll
            for (int r = 0; r < 16; r++) gs[r] += __shfl_xor_sync(0xffffffffu, gs[r], off);
            #pragma unroll
            for (int p = 0; p < 4; p++) ms[p] += __shfl_xor_sync(0xffffffffu, ms[p], off);
        }

        float hn[4];
        #pragma unroll
        for (int p = 0; p < 4; p++) {
            float iv = sigmoidf_(gs[p * 4 + 0] + cb_s[p * 4 + 0]);
            float fv = sigmoidf_(gs[p * 4 + 1] + cb_s[p * 4 + 1]);
            float ov = sigmoidf_(gs[p * 4 + 2] + cb_s[p * 4 + 2]);
            float gv = tanhf(gs[p * 4 + 3] + cb_s[p * 4 + 3]);
            float mv = tanhf(ms[p] + bb_s[p]);
            c[p] = fv * c[p] + iv * gv + SCALE_C * mv;
            hn[p] = ov * tanhf(c[p]);
        }

        if (lane < 4) {
            float v = hn[lane];
            g_h[rb ^ 1][b * 256 + o0 + lane] = v;
            out[((size_t)b * T_DIM + t) * 256 + o0 + lane] = v;
            if (t == T_DIM - 1) {
                size_t tail = (size_t)B_DIM * T_DIM * H_DIM;
                if (out_size >= (int)(tail + 2 * B_DIM * H_DIM)) {
                    out[tail + b * 256 + o0 + lane] = v;
                    out[tail + B_DIM * H_DIM + b * 256 + o0 + lane] = c[lane];
                }
            }
        }
    }
}

// ---------------- launch ----------------
extern "C" void kernel_launch(void* const* d_in, const int* in_sizes, int n_in,
                              void* d_out, int out_size) {
    const float* x  = (const float*)d_in[0];
    const float* Ww = (const float*)d_in[1];
    const float* Wb = (const float*)d_in[2];
    const float* Uw = (const float*)d_in[3];
    const float* Ub = (const float*)d_in[4];
    const float* Bw = (const float*)d_in[5];
    const float* Bb = (const float*)d_in[6];
    float* out = (float*)d_out;

    cudaFuncSetAttribute(gemm_P_kernel, cudaFuncAttributeMaxDynamicSharedMemorySize, SMEM_DYN);

    cvt_x_kernel<<<1024, 512>>>(x);
    transpose_B_kernel<<<dim3(8, 8, 256), dim3(32, 8)>>>(Bw);
    gemm_P_kernel<<<dim3(64, 512), 256, SMEM_DYN>>>();
    scan_kernel<<<128, 256>>>(x, Ww, Wb, Uw, Ub, Bb, out, out_size);
}

// round 8
// speedup vs baseline: 1.7250x; 1.0071x over previous
#include <cuda_runtime.h>
#include <cuda_fp16.h>
#include <cstdint>
#include <cstddef>

// Problem dims
#define B_DIM 16
#define T_DIM 512
#define D_DIM 256
#define H_DIM 256
#define SCALE_C 0.1f

// GEMM tiling: 128x128 tile, K chunks of 64 (one 128B swizzle row per chunk)
#define TILE_M 128
#define TILE_N 128
#define KC 64
#define NCHUNK 4

// ---------------- static device scratch (no allocation allowed) ----------------
__device__ __half g_P[(size_t)B_DIM * T_DIM * H_DIM * H_DIM];   // 1 GB, P[bt][o*256+h], fp16
__device__ __half g_Xh[(size_t)B_DIM * T_DIM * D_DIM];          // 4 MB, x fp16
__device__ __half g_BTh[(size_t)H_DIM * H_DIM * D_DIM];         // 32 MB, B_w^T fp16: [(o*256+h)][d]
__device__ float g_h[2][B_DIM * H_DIM];                         // double-buffered hidden state
__device__ unsigned g_flag[2][64];                              // per-block arrival flags (2 groups)

// ---------------- helpers ----------------
__device__ __forceinline__ uint32_t smem_u32(const void* p) {
    uint32_t a;
    asm("{ .reg .u64 t; cvta.to.shared.u64 t, %1; cvt.u32.u64 %0, t; }" : "=r"(a) : "l"(p));
    return a;
}
// swizzled offset within a 128B-row tile: row*128 + (kbyte ^ ((row<<4)&0x70))
__device__ __forceinline__ uint32_t swz(int row, int kbyte) {
    return (uint32_t)(row * 128 + (kbyte ^ ((row << 4) & 0x70)));
}
__device__ __forceinline__ void cp_async16(uint32_t saddr, const void* gaddr) {
    asm volatile("cp.async.cg.shared.global [%0], [%1], 16;" :: "r"(saddr), "l"(gaddr) : "memory");
}
#define CP_COMMIT() asm volatile("cp.async.commit_group;" ::: "memory")
#define CP_WAIT(n)  asm volatile("cp.async.wait_group %0;" :: "n"(n) : "memory")

__device__ __forceinline__ void ldsm_x4(uint32_t* r, uint32_t addr) {
    asm volatile("ldmatrix.sync.aligned.m8n8.x4.shared.b16 {%0,%1,%2,%3}, [%4];"
                 : "=r"(r[0]), "=r"(r[1]), "=r"(r[2]), "=r"(r[3]) : "r"(addr));
}
__device__ __forceinline__ void ldsm_x2(uint32_t* r, uint32_t addr) {
    asm volatile("ldmatrix.sync.aligned.m8n8.x2.shared.b16 {%0,%1}, [%2];"
                 : "=r"(r[0]), "=r"(r[1]) : "r"(addr));
}
__device__ __forceinline__ void mma16816(float* c, const uint32_t* a, const uint32_t* b) {
    asm volatile("mma.sync.aligned.m16n8k16.row.col.f32.f16.f16.f32 "
                 "{%0,%1,%2,%3}, {%4,%5,%6,%7}, {%8,%9}, {%0,%1,%2,%3};"
                 : "+f"(c[0]), "+f"(c[1]), "+f"(c[2]), "+f"(c[3])
                 : "r"(a[0]), "r"(a[1]), "r"(a[2]), "r"(a[3]), "r"(b[0]), "r"(b[1]));
}

// ---------------- prep kernels ----------------
__global__ void cvt_x_kernel(const float* __restrict__ x) {
    int n = B_DIM * T_DIM * D_DIM;
    for (int i = blockIdx.x * blockDim.x + threadIdx.x; i < n; i += gridDim.x * blockDim.x)
        g_Xh[i] = __float2half_rn(x[i]);
}

__global__ void transpose_B_kernel(const float* __restrict__ Bw) {
    __shared__ float tile[32][33];
    int o = blockIdx.z;
    int h0 = blockIdx.x * 32, d0 = blockIdx.y * 32;
    int tx = threadIdx.x, ty = threadIdx.y;
    #pragma unroll
    for (int i = 0; i < 32; i += 8)
        tile[ty + i][tx] = Bw[(size_t)o * 65536 + (size_t)(d0 + ty + i) * 256 + h0 + tx];
    __syncthreads();
    #pragma unroll
    for (int i = 0; i < 32; i += 8)
        g_BTh[((size_t)o * 256 + h0 + ty + i) * 256 + d0 + tx] = __float2half_rn(tile[tx][ty + i]);
}

// ---------------- fp16 mma.sync GEMM: P[8192,65536] = Xh * BTh^T ----------------
// 256 threads, 8 warps (2x4): warp tile 64x32. cp.async double-buffered K chunks.
// blockIdx.x = M-tile (64, fast) -> same-N blocks co-scheduled; x stays in L2.
#define CH_BYTES (128 * 128)                 // 16 KB per chunk per operand
#define SMEM_DYN (4 * CH_BYTES + 1024)

__global__ __launch_bounds__(256, 2) void gemm_P_kernel() {
    extern __shared__ char dynsmem[];
    uint32_t base = (smem_u32(dynsmem) + 1023u) & ~1023u;
    uint32_t aoff[2] = { base, base + CH_BYTES };
    uint32_t boff[2] = { base + 2 * CH_BYTES, base + 3 * CH_BYTES };

    int tid = threadIdx.x;
    int wid = tid >> 5, lane = tid & 31;
    int gm0 = blockIdx.x * TILE_M;
    int gn0 = blockIdx.y * TILE_N;
    int wm = (wid >> 2) * 64;
    int wn = (wid & 3) * 32;

    const __half* Asrc = g_Xh + (size_t)gm0 * 256;
    const __half* Bsrc = g_BTh + (size_t)gn0 * 256;

    auto load_chunk = [&](int kc, int buf) {
        int k0 = kc * KC;
        #pragma unroll
        for (int it = 0; it < 4; it++) {
            int i = tid + it * 256;
            int r = i >> 3, c16 = i & 7;
            cp_async16(aoff[buf] + swz(r, c16 * 16), &Asrc[(size_t)r * 256 + k0 + c16 * 8]);
        }
        #pragma unroll
        for (int it = 0; it < 4; it++) {
            int i = tid + it * 256;
            int r = i >> 3, c16 = i & 7;
            cp_async16(boff[buf] + swz(r, c16 * 16), &Bsrc[(size_t)r * 256 + k0 + c16 * 8]);
        }
        CP_COMMIT();
    };

    float acc[4][4][4];
    #pragma unroll
    for (int mi = 0; mi < 4; mi++)
        #pragma unroll
        for (int ni = 0; ni < 4; ni++)
            #pragma unroll
            for (int e = 0; e < 4; e++) acc[mi][ni][e] = 0.f;

    int la = (lane & 7) + ((lane >> 3) & 1) * 8;   // A row-in-16
    int ka = ((lane >> 4) & 1) * 8;                // A k offset (halves)
    int lb = lane & 7;                             // B row-in-8
    int kb = ((lane >> 3) & 1) * 8;                // B k offset (halves)

    load_chunk(0, 0);

    #pragma unroll
    for (int kc = 0; kc < NCHUNK; kc++) {
        int buf = kc & 1;
        if (kc + 1 < NCHUNK) load_chunk(kc + 1, (kc + 1) & 1);
        if (kc + 1 < NCHUNK) { CP_WAIT(1); } else { CP_WAIT(0); }
        __syncthreads();

        uint32_t ab = aoff[buf], bb = boff[buf];
        #pragma unroll
        for (int ks = 0; ks < 4; ks++) {
            uint32_t afr[4][4], bfr[4][2];
            #pragma unroll
            for (int mi = 0; mi < 4; mi++) {
                int row = wm + mi * 16 + la;
                ldsm_x4(afr[mi], ab + swz(row, (ks * 16 + ka) * 2));
            }
            #pragma unroll
            for (int ni = 0; ni < 4; ni++) {
                int row = wn + ni * 8 + lb;
                ldsm_x2(bfr[ni], bb + swz(row, (ks * 16 + kb) * 2));
            }
            #pragma unroll
            for (int mi = 0; mi < 4; mi++)
                #pragma unroll
                for (int ni = 0; ni < 4; ni++)
                    mma16816(acc[mi][ni], afr[mi], bfr[ni]);
        }
        __syncthreads();
    }

    // epilogue: stage fp16 tile in smem (pitch 136 halves), then coalesced uint4 stores
    {
        __half* sm = (__half*)dynsmem;
        int q = lane >> 2, p = lane & 3;
        #pragma unroll
        for (int mi = 0; mi < 4; mi++)
            #pragma unroll
            for (int ni = 0; ni < 4; ni++) {
                int col = wn + ni * 8 + p * 2;
                int r0 = wm + mi * 16 + q;
                *(__half2*)&sm[r0 * 136 + col] =
                    __floats2half2_rn(acc[mi][ni][0], acc[mi][ni][1]);
                *(__half2*)&sm[(r0 + 8) * 136 + col] =
                    __floats2half2_rn(acc[mi][ni][2], acc[mi][ni][3]);
            }
        __syncthreads();
        #pragma unroll
        for (int j = 0; j < 8; j++) {
            int i = tid + j * 256;
            int r = i >> 4, c16 = i & 15;
            uint4 v = *(const uint4*)&sm[r * 136 + c16 * 8];
            *(uint4*)&g_P[(size_t)(gm0 + r) * 65536 + gn0 + c16 * 8] = v;
        }
    }
}

// ---------------- fast activations (MUFU path; ~1e-6 err, negligible here) ---------
__device__ __forceinline__ float sigmoid_fast(float v) { return 1.0f / (1.0f + __expf(-v)); }
__device__ __forceinline__ float tanh_fast(float v)    { return 1.0f - 2.0f / (1.0f + __expf(2.0f * v)); }

// ---------------- persistent scan kernel ----------------
// 128 blocks x 256 threads. Block = (o-group of 4) x (b-octet). Warp = one b, 4 o's.
// Blocks 0-63 handle b0-7, 64-127 handle b8-15 -> independent flag-barrier groups.
// Flag barrier: each block store-releases its own word; all threads poll the 64
// flags cooperatively (no same-address atomic serialization).
__global__ __launch_bounds__(256) void scan_kernel(
    const float* __restrict__ x,
    const float* __restrict__ Ww, const float* __restrict__ Wb,
    const float* __restrict__ Uw, const float* __restrict__ Ub,
    const float* __restrict__ Bbias,
    float* __restrict__ out, int out_size)
{
    __shared__ float Us[16][256];
    __shared__ float Ws[16][256];
    __shared__ float cb_s[16];
    __shared__ float bb_s[4];
    __shared__ unsigned s_base;

    int tid = threadIdx.x;
    int wid = tid >> 5, lane = tid & 31;
    int bid = blockIdx.x;
    int grp = bid >> 6;
    int slot = bid & 63;
    int o0 = slot * 4;
    int b  = grp * 8 + wid;

    if (tid == 0) s_base = *(volatile unsigned*)&g_flag[grp][slot];  // own slot; stable

    for (int i = tid; i < 4096; i += 256) {
        int r = i >> 8, k = i & 255;
        int p = r >> 2, gi = r & 3;
        int grow = gi * 256 + o0 + p;
        Us[r][k] = Uw[(size_t)grow * 256 + k];
        Ws[r][k] = Ww[(size_t)grow * 256 + k];
    }
    if (tid < 16) {
        int p = tid >> 2, gi = tid & 3;
        int grow = gi * 256 + o0 + p;
        cb_s[tid] = Wb[grow] + Ub[grow];
    }
    if (tid < 4) bb_s[tid] = Bbias[o0 + tid];

    float c[4] = {0.f, 0.f, 0.f, 0.f};
    if (lane < 4) g_h[0][b * 256 + o0 + lane] = 0.f;
    __syncthreads();
    unsigned base = s_base;
    if (tid == 0) {                                   // arrive: h0 written
        __threadfence();
        *(volatile unsigned*)&g_flag[grp][slot] = base + 1;
    }

    int pollidx = tid & 63;
    const volatile unsigned* myflag = &g_flag[grp][pollidx];

    for (int t = 0; t < T_DIM; t++) {
        // pre-wait work: x-only gates + P prefetch (overlaps other blocks' arrival)
        float xr[8];
        const float* xp = x + ((size_t)b * T_DIM + t) * 256 + lane * 8;
        *(float4*)&xr[0] = *(const float4*)xp;
        *(float4*)&xr[4] = *(const float4*)(xp + 4);

        uint4 pr[4];
        const __half* pp = g_P + (size_t)(b * T_DIM + t) * 65536 + (size_t)o0 * 256 + lane * 8;
        #pragma unroll
        for (int p = 0; p < 4; p++) pr[p] = *(const uint4*)(pp + (size_t)p * 256);

        float gs[16];
        #pragma unroll
        for (int r = 0; r < 16; r++) {
            float4 w0 = *(const float4*)&Ws[r][lane * 8];
            float4 w1 = *(const float4*)&Ws[r][lane * 8 + 4];
            gs[r] = w0.x * xr[0] + w0.y * xr[1] + w0.z * xr[2] + w0.w * xr[3]
                  + w1.x * xr[4] + w1.y * xr[5] + w1.z * xr[6] + w1.w * xr[7];
        }

        // flag barrier wait: all blocks wrote h(t-1)
        {
            unsigned target = base + 1 + (unsigned)t;
            bool ok;
            do {
                unsigned v = *myflag;
                ok = ((int)(v - target) >= 0);
            } while (!__syncthreads_and(ok));
            __threadfence();   // acquire: order h reads after flag observation
        }

        int rb = t & 1;
        float hr[8];
        const float* hp = &g_h[rb][b * 256 + lane * 8];
        *(float4*)&hr[0] = *(const float4*)hp;
        *(float4*)&hr[4] = *(const float4*)(hp + 4);

        #pragma unroll
        for (int r = 0; r < 16; r++) {
            float4 u0 = *(const float4*)&Us[r][lane * 8];
            float4 u1 = *(const float4*)&Us[r][lane * 8 + 4];
            gs[r] += u0.x * hr[0] + u0.y * hr[1] + u0.z * hr[2] + u0.w * hr[3]
                   + u1.x * hr[4] + u1.y * hr[5] + u1.z * hr[6] + u1.w * hr[7];
        }

        float ms[4];
        #pragma unroll
        for (int p = 0; p < 4; p++) {
            const __half2* pb = (const __half2*)&pr[p];
            float s = 0.f;
            #pragma unroll
            for (int j = 0; j < 4; j++) {
                float2 f = __half22float2(pb[j]);
                s += f.x * hr[2 * j] + f.y * hr[2 * j + 1];
            }
            ms[p] = s;
        }

        #pragma unroll
        for (int off = 16; off > 0; off >>= 1) {
            #pragma unroll
            for (int r = 0; r < 16; r++) gs[r] += __shfl_xor_sync(0xffffffffu, gs[r], off);
            #pragma unroll
            for (int p = 0; p < 4; p++) ms[p] += __shfl_xor_sync(0xffffffffu, ms[p], off);
        }

        float hn[4];
        #pragma unroll
        for (int p = 0; p < 4; p++) {
            float iv = sigmoid_fast(gs[p * 4 + 0] + cb_s[p * 4 + 0]);
            float fv = sigmoid_fast(gs[p * 4 + 1] + cb_s[p * 4 + 1]);
            float ov = sigmoid_fast(gs[p * 4 + 2] + cb_s[p * 4 + 2]);
            float gv = tanh_fast(gs[p * 4 + 3] + cb_s[p * 4 + 3]);
            float mv = tanh_fast(ms[p] + bb_s[p]);
            c[p] = fv * c[p] + iv * gv + SCALE_C * mv;
            hn[p] = ov * tanh_fast(c[p]);
        }

        if (lane < 4) {
            float v = hn[lane];
            g_h[rb ^ 1][b * 256 + o0 + lane] = v;
            out[((size_t)b * T_DIM + t) * 256 + o0 + lane] = v;
            if (t == T_DIM - 1) {
                size_t tail = (size_t)B_DIM * T_DIM * H_DIM;
                if (out_size >= (int)(tail + 2 * B_DIM * H_DIM)) {
                    out[tail + b * 256 + o0 + lane] = v;
                    out[tail + B_DIM * H_DIM + b * 256 + o0 + lane] = c[lane];
                }
            }
        }

        // arrive: h(t) written -> release peers before next pre-work
        __syncthreads();
        if (tid == 0) {
            __threadfence();
            *(volatile unsigned*)&g_flag[grp][slot] = base + 2 + (unsigned)t;
        }
    }
}

// ---------------- launch ----------------
extern "C" void kernel_launch(void* const* d_in, const int* in_sizes, int n_in,
                              void* d_out, int out_size) {
    const float* x  = (const float*)d_in[0];
    const float* Ww = (const float*)d_in[1];
    const float* Wb = (const float*)d_in[2];
    const float* Uw = (const float*)d_in[3];
    const float* Ub = (const float*)d_in[4];
    const float* Bw = (const float*)d_in[5];
    const float* Bb = (const float*)d_in[6];
    float* out = (float*)d_out;

    cudaFuncSetAttribute(gemm_P_kernel, cudaFuncAttributeMaxDynamicSharedMemorySize, SMEM_DYN);

    cvt_x_kernel<<<1024, 512>>>(x);
    transpose_B_kernel<<<dim3(8, 8, 256), dim3(32, 8)>>>(Bw);
    gemm_P_kernel<<<dim3(64, 512), 256, SMEM_DYN>>>();
    scan_kernel<<<128, 256>>>(x, Ww, Wb, Uw, Ub, Bb, out, out_size);
}